// round 6
// baseline (speedup 1.0000x reference)
#include <cuda_runtime.h>
#include <cuda_fp16.h>
#include <cstdint>

#define NN 100000
#define EE 1600000
#define NEG_SLOPE 0.2f
#define LN_EPS 1e-5f
#define NCHUNK 98  // ceil(NN/1024)

// ---------------- scratch (device globals; no allocation allowed) ----------------
__device__ __half  g_feat16[(size_t)NN * 128]; // h @ W in fp16 (25.6 MB, L2-resident)
__device__ float   g_el[NN * 2];
__device__ float   g_er[NN * 2];
__device__ int     g_deg[NN];
__device__ int     g_rowptr[NN + 1];
__device__ int     g_cursor[NN];
__device__ int     g_chunk_sum[128];
__device__ int     g_chunk_excl[128];
__device__ float4  g_csr[EE];                  // {src(bits), exp_e_head0, exp_e_head1, pad}

// ---------------- 0: zero degree counters ----------------
__global__ void zero_deg_kernel() {
    int i = blockIdx.x * blockDim.x + threadIdx.x;
    if (i < NN) g_deg[i] = 0;
}

// ---------------- 1: feat = h@W + el/er dots (packed f32x2 FFMA2) ----------------
// Block = 64 rows x 128 cols, 256 threads (8 warps). K tiled by 32.
// h staged transposed AND pre-splatted ({a,a} float2 per k,row) -> broadcast 8B LDS;
// W tile rows read as ulonglong2 -> free f32x2 operand pairs.
#define KT 32
#define HS2 66   // float2 stride per k-row of splatted h tile (64 pairs + 2 pad)
__device__ __forceinline__ void fma2(unsigned long long& acc, unsigned long long a,
                                     unsigned long long b) {
    asm("fma.rn.f32x2 %0, %1, %2, %0;" : "+l"(acc) : "l"(a), "l"(b));
}
__global__ void gemm_kernel(const float* __restrict__ h, const float* __restrict__ W,
                            const float* __restrict__ attn_l, const float* __restrict__ attn_r) {
    __shared__ float  Wsh[KT * 128];           // 16 KB
    __shared__ float2 hsh[KT * HS2];           // 16.9 KB (splatted: hsh[k*HS2+r] = {a,a})
    int tid = threadIdx.x;
    int lane = tid & 31, wid = tid >> 5;
    int row0 = blockIdx.x * 64;

    unsigned long long acc[8][2];
#pragma unroll
    for (int r = 0; r < 8; r++) { acc[r][0] = 0ULL; acc[r][1] = 0ULL; }

    for (int t = 0; t < 4; t++) {
        __syncthreads();
        {
            const float4* Wg = (const float4*)(W + t * KT * 128);
            float4* Ws = (float4*)Wsh;
            for (int j = tid; j < KT * 32; j += 256) Ws[j] = Wg[j];
        }
        for (int j = tid; j < 64 * (KT / 4); j += 256) {
            int r = j >> 3, c4 = j & 7;
            int row = row0 + r;
            float4 v = make_float4(0.f, 0.f, 0.f, 0.f);
            if (row < NN) v = *(const float4*)(h + (size_t)row * 128 + t * KT + c4 * 4);
            hsh[(c4 * 4 + 0) * HS2 + r] = make_float2(v.x, v.x);
            hsh[(c4 * 4 + 1) * HS2 + r] = make_float2(v.y, v.y);
            hsh[(c4 * 4 + 2) * HS2 + r] = make_float2(v.z, v.z);
            hsh[(c4 * 4 + 3) * HS2 + r] = make_float2(v.w, v.w);
        }
        __syncthreads();
#pragma unroll 4
        for (int kk = 0; kk < KT; kk++) {
            ulonglong2 b = *(const ulonglong2*)(Wsh + kk * 128 + lane * 4);
            const ulonglong2* ap = (const ulonglong2*)(hsh + kk * HS2 + wid * 8);
            ulonglong2 a01 = ap[0], a23 = ap[1], a45 = ap[2], a67 = ap[3];
            fma2(acc[0][0], a01.x, b.x); fma2(acc[0][1], a01.x, b.y);
            fma2(acc[1][0], a01.y, b.x); fma2(acc[1][1], a01.y, b.y);
            fma2(acc[2][0], a23.x, b.x); fma2(acc[2][1], a23.x, b.y);
            fma2(acc[3][0], a23.y, b.x); fma2(acc[3][1], a23.y, b.y);
            fma2(acc[4][0], a45.x, b.x); fma2(acc[4][1], a45.x, b.y);
            fma2(acc[5][0], a45.y, b.x); fma2(acc[5][1], a45.y, b.y);
            fma2(acc[6][0], a67.x, b.x); fma2(acc[6][1], a67.x, b.y);
            fma2(acc[7][0], a67.y, b.x); fma2(acc[7][1], a67.y, b.y);
        }
    }

    // epilogue: store feat (fp16) + per-head attention dots (fp32, from registers)
    float4 al4 = ((const float4*)attn_l)[lane];
    float4 ar4 = ((const float4*)attn_r)[lane];
#pragma unroll
    for (int r = 0; r < 8; r++) {
        int row = row0 + wid * 8 + r;
        if (row >= NN) continue;
        float2 lo = *(float2*)&acc[r][0];
        float2 hi = *(float2*)&acc[r][1];
        __half2 p0 = __floats2half2_rn(lo.x, lo.y);
        __half2 p1 = __floats2half2_rn(hi.x, hi.y);
        uint2 hv;
        hv.x = *(uint32_t*)&p0;
        hv.y = *(uint32_t*)&p1;
        *(uint2*)(g_feat16 + (size_t)row * 128 + lane * 4) = hv;
        float elp = lo.x * al4.x + lo.y * al4.y + hi.x * al4.z + hi.y * al4.w;
        float erp = lo.x * ar4.x + lo.y * ar4.y + hi.x * ar4.z + hi.y * ar4.w;
#pragma unroll
        for (int off = 8; off; off >>= 1) {   // reduce within each 16-lane half (per head)
            elp += __shfl_xor_sync(0xffffffffu, elp, off);
            erp += __shfl_xor_sync(0xffffffffu, erp, off);
        }
        if (lane == 0)       { g_el[2 * row]     = elp; g_er[2 * row]     = erp; }
        else if (lane == 16) { g_el[2 * row + 1] = elp; g_er[2 * row + 1] = erp; }
    }
}

// ---------------- 2: degree histogram ----------------
__global__ void hist_kernel(const int* __restrict__ dst) {
    int e = blockIdx.x * blockDim.x + threadIdx.x;
    if (e < EE) atomicAdd(&g_deg[dst[e]], 1);
}

// ---------------- 3a: per-chunk sums (chunk = 1024) ----------------
__global__ void chunk_sum_kernel() {
    int b = blockIdx.x, t = threadIdx.x;
    int base = b * 1024;
    int s = 0;
    for (int j = t; j < 1024; j += 256) {
        int i = base + j;
        s += (i < NN) ? g_deg[i] : 0;
    }
    __shared__ int sh[8];
#pragma unroll
    for (int off = 16; off; off >>= 1) s += __shfl_xor_sync(0xffffffffu, s, off);
    if ((t & 31) == 0) sh[t >> 5] = s;
    __syncthreads();
    if (t < 32) {
        int v = (t < 8) ? sh[t] : 0;
#pragma unroll
        for (int off = 4; off; off >>= 1) v += __shfl_xor_sync(0xffffffffu, v, off);
        if (t == 0) g_chunk_sum[b] = v;
    }
}

// ---------------- 3b: scan chunk sums (1 block) ----------------
__global__ void scan_chunks_kernel() {
    __shared__ int sh[128];
    int t = threadIdx.x;
    int v = (t < NCHUNK) ? g_chunk_sum[t] : 0;
    sh[t] = v;
    __syncthreads();
    for (int off = 1; off < 128; off <<= 1) {
        int a = (t >= off) ? sh[t - off] : 0;
        __syncthreads();
        sh[t] += a;
        __syncthreads();
    }
    if (t < NCHUNK) g_chunk_excl[t] = sh[t] - v;
}

// ---------------- 3c: finalize row_ptr / cursor ----------------
__global__ void scan_final_kernel() {
    int i = blockIdx.x * 1024 + threadIdx.x;
    int lane = threadIdx.x & 31, wid = threadIdx.x >> 5;
    int v = (i < NN) ? g_deg[i] : 0;
    int x = v;
#pragma unroll
    for (int off = 1; off < 32; off <<= 1) {
        int y = __shfl_up_sync(0xffffffffu, x, off);
        if (lane >= off) x += y;
    }
    __shared__ int sh[32];
    if (lane == 31) sh[wid] = x;
    __syncthreads();
    if (wid == 0) {
        int y = sh[lane];
#pragma unroll
        for (int off = 1; off < 32; off <<= 1) {
            int z = __shfl_up_sync(0xffffffffu, y, off);
            if (lane >= off) y += z;
        }
        sh[lane] = y;
    }
    __syncthreads();
    int incl = x + (wid ? sh[wid - 1] : 0);
    int base = g_chunk_excl[blockIdx.x];
    if (i < NN) {
        int excl = base + incl - v;
        g_rowptr[i] = excl;
        g_cursor[i] = excl;
    }
    if (i == NN - 1) g_rowptr[NN] = base + incl;
}

// ---------------- 4: scatter edges into CSR order with exp(logit) ----------------
__global__ void scatter_kernel(const int* __restrict__ src, const int* __restrict__ dst) {
    int e = blockIdx.x * blockDim.x + threadIdx.x;
    if (e >= EE) return;
    int s = src[e], d = dst[e];
    int p = atomicAdd(&g_cursor[d], 1);
    float e0 = g_el[2 * s]     + g_er[2 * d];
    float e1 = g_el[2 * s + 1] + g_er[2 * d + 1];
    e0 = (e0 > 0.f) ? e0 : NEG_SLOPE * e0;
    e1 = (e1 > 0.f) ? e1 : NEG_SLOPE * e1;
    g_csr[p] = make_float4(__int_as_float(s), __expf(e0), __expf(e1), 0.f);
}

// ---------------- 5: per-node weighted aggregate + fused LayerNorm ----------------
// One warp per node, single pass. Lanes 0-15 = head0 cols (0-63), 16-31 = head1.
__global__ void agg_ln_kernel(const float* __restrict__ bias, const float* __restrict__ gamma,
                              const float* __restrict__ beta, float* __restrict__ out) {
    int gwarp = (blockIdx.x * blockDim.x + threadIdx.x) >> 5;
    int lane = threadIdx.x & 31;
    if (gwarp >= NN) return;
    int beg = g_rowptr[gwarp], end = g_rowptr[gwarp + 1];
    bool h1 = (lane >= 16);

    float4 acc = make_float4(0.f, 0.f, 0.f, 0.f);
    float wsum = 0.f;
    int i = beg;
    for (; i + 2 <= end; i += 2) {
        float4 c0 = g_csr[i], c1 = g_csr[i + 1];
        uint2 u0 = ((const uint2*)(g_feat16 + (size_t)__float_as_int(c0.x) * 128))[lane];
        uint2 u1 = ((const uint2*)(g_feat16 + (size_t)__float_as_int(c1.x) * 128))[lane];
        float2 v0a = __half22float2(*(__half2*)&u0.x);
        float2 v0b = __half22float2(*(__half2*)&u0.y);
        float2 v1a = __half22float2(*(__half2*)&u1.x);
        float2 v1b = __half22float2(*(__half2*)&u1.y);
        float w0 = h1 ? c0.z : c0.y;
        float w1 = h1 ? c1.z : c1.y;
        wsum += w0 + w1;
        acc.x += w0 * v0a.x + w1 * v1a.x;
        acc.y += w0 * v0a.y + w1 * v1a.y;
        acc.z += w0 * v0b.x + w1 * v1b.x;
        acc.w += w0 * v0b.y + w1 * v1b.y;
    }
    if (i < end) {
        float4 c0 = g_csr[i];
        uint2 u0 = ((const uint2*)(g_feat16 + (size_t)__float_as_int(c0.x) * 128))[lane];
        float2 v0a = __half22float2(*(__half2*)&u0.x);
        float2 v0b = __half22float2(*(__half2*)&u0.y);
        float w0 = h1 ? c0.z : c0.y;
        wsum += w0;
        acc.x += w0 * v0a.x; acc.y += w0 * v0a.y;
        acc.z += w0 * v0b.x; acc.w += w0 * v0b.y;
    }
    float inv = (end > beg) ? 1.0f / wsum : 0.f;

    float4 b4 = ((const float4*)bias)[lane];
    float4 x;
    x.x = acc.x * inv + b4.x; x.y = acc.y * inv + b4.y;
    x.z = acc.z * inv + b4.z; x.w = acc.w * inv + b4.w;

    float s = x.x + x.y + x.z + x.w;
#pragma unroll
    for (int off = 16; off; off >>= 1) s += __shfl_xor_sync(0xffffffffu, s, off);
    float mu = s * (1.f / 128.f);
    float dx0 = x.x - mu, dx1 = x.y - mu, dx2 = x.z - mu, dx3 = x.w - mu;
    float ss = dx0 * dx0 + dx1 * dx1 + dx2 * dx2 + dx3 * dx3;
#pragma unroll
    for (int off = 16; off; off >>= 1) ss += __shfl_xor_sync(0xffffffffu, ss, off);
    float istd = rsqrtf(ss * (1.f / 128.f) + LN_EPS);

    float4 g4 = ((const float4*)gamma)[lane];
    float4 be4 = ((const float4*)beta)[lane];
    float4 y;
    y.x = g4.x * dx0 * istd + be4.x;
    y.y = g4.y * dx1 * istd + be4.y;
    y.z = g4.z * dx2 * istd + be4.z;
    y.w = g4.w * dx3 * istd + be4.w;
    ((float4*)(out + (size_t)gwarp * 128))[lane] = y;
}

// ---------------- launch ----------------
extern "C" void kernel_launch(void* const* d_in, const int* in_sizes, int n_in,
                              void* d_out, int out_size) {
    const float* h      = (const float*)d_in[0];
    const int*   src    = (const int*)d_in[1];
    const int*   dst    = (const int*)d_in[2];
    const float* W      = (const float*)d_in[3];
    const float* attn_l = (const float*)d_in[4];
    const float* attn_r = (const float*)d_in[5];
    const float* bias   = (const float*)d_in[6];
    const float* gamma  = (const float*)d_in[7];
    const float* beta   = (const float*)d_in[8];
    float* out = (float*)d_out;

    zero_deg_kernel<<<(NN + 255) / 256, 256>>>();
    gemm_kernel<<<(NN + 63) / 64, 256>>>(h, W, attn_l, attn_r);
    hist_kernel<<<(EE + 255) / 256, 256>>>(dst);
    chunk_sum_kernel<<<NCHUNK, 256>>>();
    scan_chunks_kernel<<<1, 128>>>();
    scan_final_kernel<<<NCHUNK, 1024>>>();
    scatter_kernel<<<(EE + 255) / 256, 256>>>(src, dst);
    agg_ln_kernel<<<(NN * 32 + 255) / 256, 256>>>(bias, gamma, beta, out);
}

// round 7
// speedup vs baseline: 1.1795x; 1.1795x over previous
#include <cuda_runtime.h>
#include <cuda_fp16.h>
#include <cstdint>

#define NN 100000
#define EE 1600000
#define NEG_SLOPE 0.2f
#define LN_EPS 1e-5f
#define NCHUNK 98  // ceil(NN/1024)

// ---------------- scratch (device globals; no allocation allowed) ----------------
__device__ __half  g_feat16[(size_t)NN * 128]; // h @ W in fp16 (25.6 MB, L2-resident)
__device__ float   g_el[NN * 2];
__device__ float   g_er[NN * 2];
__device__ int     g_deg[NN];
__device__ int     g_rowptr[NN + 1];
__device__ int     g_cursor[NN];
__device__ int     g_chunk_sum[128];
__device__ int     g_chunk_excl[128];
__device__ uint2   g_csr[EE];                  // {src, half2{exp_e0, exp_e1}} -- 8B/edge

// ---------------- 0: zero degree counters ----------------
__global__ void zero_deg_kernel() {
    int i = blockIdx.x * blockDim.x + threadIdx.x;
    if (i < NN) g_deg[i] = 0;
}

// ---------------- 1: feat = h@W + el/er dots (FFMA, known-good R5 version) ----------------
#define KT 32
#define HS 68   // padded row stride (floats) for transposed h tile
__global__ void gemm_kernel(const float* __restrict__ h, const float* __restrict__ W,
                            const float* __restrict__ attn_l, const float* __restrict__ attn_r) {
    __shared__ float Wsh[KT * 128];   // 16 KB
    __shared__ float hsh[KT * HS];    // 8.7 KB
    int tid = threadIdx.x;
    int lane = tid & 31, wid = tid >> 5;
    int row0 = blockIdx.x * 64;

    float4 acc[8];
#pragma unroll
    for (int r = 0; r < 8; r++) acc[r] = make_float4(0.f, 0.f, 0.f, 0.f);

    for (int t = 0; t < 4; t++) {
        __syncthreads();
        {
            const float4* Wg = (const float4*)(W + t * KT * 128);
            float4* Ws = (float4*)Wsh;
            for (int j = tid; j < KT * 32; j += 256) Ws[j] = Wg[j];
        }
        for (int j = tid; j < 64 * (KT / 4); j += 256) {
            int r = j >> 3, c4 = j & 7;
            int row = row0 + r;
            float4 v = make_float4(0.f, 0.f, 0.f, 0.f);
            if (row < NN) v = *(const float4*)(h + (size_t)row * 128 + t * KT + c4 * 4);
            hsh[(c4 * 4 + 0) * HS + r] = v.x;
            hsh[(c4 * 4 + 1) * HS + r] = v.y;
            hsh[(c4 * 4 + 2) * HS + r] = v.z;
            hsh[(c4 * 4 + 3) * HS + r] = v.w;
        }
        __syncthreads();
#pragma unroll 4
        for (int kk = 0; kk < KT; kk++) {
            float4 b  = ((const float4*)(Wsh + kk * 128))[lane];
            float4 alo = *(const float4*)(hsh + kk * HS + wid * 8);
            float4 ahi = *(const float4*)(hsh + kk * HS + wid * 8 + 4);
            acc[0].x += alo.x * b.x; acc[0].y += alo.x * b.y; acc[0].z += alo.x * b.z; acc[0].w += alo.x * b.w;
            acc[1].x += alo.y * b.x; acc[1].y += alo.y * b.y; acc[1].z += alo.y * b.z; acc[1].w += alo.y * b.w;
            acc[2].x += alo.z * b.x; acc[2].y += alo.z * b.y; acc[2].z += alo.z * b.z; acc[2].w += alo.z * b.w;
            acc[3].x += alo.w * b.x; acc[3].y += alo.w * b.y; acc[3].z += alo.w * b.z; acc[3].w += alo.w * b.w;
            acc[4].x += ahi.x * b.x; acc[4].y += ahi.x * b.y; acc[4].z += ahi.x * b.z; acc[4].w += ahi.x * b.w;
            acc[5].x += ahi.y * b.x; acc[5].y += ahi.y * b.y; acc[5].z += ahi.y * b.z; acc[5].w += ahi.y * b.w;
            acc[6].x += ahi.z * b.x; acc[6].y += ahi.z * b.y; acc[6].z += ahi.z * b.z; acc[6].w += ahi.z * b.w;
            acc[7].x += ahi.w * b.x; acc[7].y += ahi.w * b.y; acc[7].z += ahi.w * b.z; acc[7].w += ahi.w * b.w;
        }
    }

    float4 al4 = ((const float4*)attn_l)[lane];
    float4 ar4 = ((const float4*)attn_r)[lane];
#pragma unroll
    for (int r = 0; r < 8; r++) {
        int row = row0 + wid * 8 + r;
        if (row >= NN) continue;
        __half2 p0 = __floats2half2_rn(acc[r].x, acc[r].y);
        __half2 p1 = __floats2half2_rn(acc[r].z, acc[r].w);
        uint2 hv;
        hv.x = *(uint32_t*)&p0;
        hv.y = *(uint32_t*)&p1;
        *(uint2*)(g_feat16 + (size_t)row * 128 + lane * 4) = hv;
        float elp = acc[r].x * al4.x + acc[r].y * al4.y + acc[r].z * al4.z + acc[r].w * al4.w;
        float erp = acc[r].x * ar4.x + acc[r].y * ar4.y + acc[r].z * ar4.z + acc[r].w * ar4.w;
#pragma unroll
        for (int off = 8; off; off >>= 1) {
            elp += __shfl_xor_sync(0xffffffffu, elp, off);
            erp += __shfl_xor_sync(0xffffffffu, erp, off);
        }
        if (lane == 0)       { g_el[2 * row]     = elp; g_er[2 * row]     = erp; }
        else if (lane == 16) { g_el[2 * row + 1] = elp; g_er[2 * row + 1] = erp; }
    }
}

// ---------------- 2: degree histogram ----------------
__global__ void hist_kernel(const int* __restrict__ dst) {
    int e = blockIdx.x * blockDim.x + threadIdx.x;
    if (e < EE) atomicAdd(&g_deg[dst[e]], 1);
}

// ---------------- 3a: per-chunk sums (chunk = 1024) ----------------
__global__ void chunk_sum_kernel() {
    int b = blockIdx.x, t = threadIdx.x;
    int base = b * 1024;
    int s = 0;
    for (int j = t; j < 1024; j += 256) {
        int i = base + j;
        s += (i < NN) ? g_deg[i] : 0;
    }
    __shared__ int sh[8];
#pragma unroll
    for (int off = 16; off; off >>= 1) s += __shfl_xor_sync(0xffffffffu, s, off);
    if ((t & 31) == 0) sh[t >> 5] = s;
    __syncthreads();
    if (t < 32) {
        int v = (t < 8) ? sh[t] : 0;
#pragma unroll
        for (int off = 4; off; off >>= 1) v += __shfl_xor_sync(0xffffffffu, v, off);
        if (t == 0) g_chunk_sum[b] = v;
    }
}

// ---------------- 3b: scan chunk sums (1 block) ----------------
__global__ void scan_chunks_kernel() {
    __shared__ int sh[128];
    int t = threadIdx.x;
    int v = (t < NCHUNK) ? g_chunk_sum[t] : 0;
    sh[t] = v;
    __syncthreads();
    for (int off = 1; off < 128; off <<= 1) {
        int a = (t >= off) ? sh[t - off] : 0;
        __syncthreads();
        sh[t] += a;
        __syncthreads();
    }
    if (t < NCHUNK) g_chunk_excl[t] = sh[t] - v;
}

// ---------------- 3c: finalize row_ptr / cursor ----------------
__global__ void scan_final_kernel() {
    int i = blockIdx.x * 1024 + threadIdx.x;
    int lane = threadIdx.x & 31, wid = threadIdx.x >> 5;
    int v = (i < NN) ? g_deg[i] : 0;
    int x = v;
#pragma unroll
    for (int off = 1; off < 32; off <<= 1) {
        int y = __shfl_up_sync(0xffffffffu, x, off);
        if (lane >= off) x += y;
    }
    __shared__ int sh[32];
    if (lane == 31) sh[wid] = x;
    __syncthreads();
    if (wid == 0) {
        int y = sh[lane];
#pragma unroll
        for (int off = 1; off < 32; off <<= 1) {
            int z = __shfl_up_sync(0xffffffffu, y, off);
            if (lane >= off) y += z;
        }
        sh[lane] = y;
    }
    __syncthreads();
    int incl = x + (wid ? sh[wid - 1] : 0);
    int base = g_chunk_excl[blockIdx.x];
    if (i < NN) {
        int excl = base + incl - v;
        g_rowptr[i] = excl;
        g_cursor[i] = excl;
    }
    if (i == NN - 1) g_rowptr[NN] = base + incl;
}

// ---------------- 4: scatter edges into CSR order with exp(logit), 8B entries ----------------
__global__ void scatter_kernel(const int* __restrict__ src, const int* __restrict__ dst) {
    int e = blockIdx.x * blockDim.x + threadIdx.x;
    if (e >= EE) return;
    int s = src[e], d = dst[e];
    int p = atomicAdd(&g_cursor[d], 1);
    float e0 = g_el[2 * s]     + g_er[2 * d];
    float e1 = g_el[2 * s + 1] + g_er[2 * d + 1];
    e0 = (e0 > 0.f) ? e0 : NEG_SLOPE * e0;
    e1 = (e1 > 0.f) ? e1 : NEG_SLOPE * e1;
    __half2 w = __floats2half2_rn(__expf(e0), __expf(e1));
    g_csr[p] = make_uint2((uint32_t)s, *(uint32_t*)&w);
}

// ---------------- 5: per-node weighted aggregate + fused LayerNorm ----------------
// One warp per node, single pass. Lanes 0-15 = head0 cols (0-63), 16-31 = head1.
__global__ void agg_ln_kernel(const float* __restrict__ bias, const float* __restrict__ gamma,
                              const float* __restrict__ beta, float* __restrict__ out) {
    int gwarp = (blockIdx.x * blockDim.x + threadIdx.x) >> 5;
    int lane = threadIdx.x & 31;
    if (gwarp >= NN) return;
    int beg = g_rowptr[gwarp], end = g_rowptr[gwarp + 1];
    bool h1 = (lane >= 16);

    float4 acc = make_float4(0.f, 0.f, 0.f, 0.f);
    float wsum = 0.f;
    int i = beg;
    for (; i + 2 <= end; i += 2) {
        uint2 c0 = g_csr[i], c1 = g_csr[i + 1];
        uint2 u0 = ((const uint2*)(g_feat16 + (size_t)c0.x * 128))[lane];
        uint2 u1 = ((const uint2*)(g_feat16 + (size_t)c1.x * 128))[lane];
        __half2 wh0 = *(__half2*)&c0.y, wh1 = *(__half2*)&c1.y;
        float w0 = h1 ? __high2float(wh0) : __low2float(wh0);
        float w1 = h1 ? __high2float(wh1) : __low2float(wh1);
        float2 v0a = __half22float2(*(__half2*)&u0.x);
        float2 v0b = __half22float2(*(__half2*)&u0.y);
        float2 v1a = __half22float2(*(__half2*)&u1.x);
        float2 v1b = __half22float2(*(__half2*)&u1.y);
        wsum += w0 + w1;
        acc.x += w0 * v0a.x + w1 * v1a.x;
        acc.y += w0 * v0a.y + w1 * v1a.y;
        acc.z += w0 * v0b.x + w1 * v1b.x;
        acc.w += w0 * v0b.y + w1 * v1b.y;
    }
    if (i < end) {
        uint2 c0 = g_csr[i];
        uint2 u0 = ((const uint2*)(g_feat16 + (size_t)c0.x * 128))[lane];
        __half2 wh0 = *(__half2*)&c0.y;
        float w0 = h1 ? __high2float(wh0) : __low2float(wh0);
        float2 v0a = __half22float2(*(__half2*)&u0.x);
        float2 v0b = __half22float2(*(__half2*)&u0.y);
        wsum += w0;
        acc.x += w0 * v0a.x; acc.y += w0 * v0a.y;
        acc.z += w0 * v0b.x; acc.w += w0 * v0b.y;
    }
    float inv = (end > beg) ? 1.0f / wsum : 0.f;

    float4 b4 = ((const float4*)bias)[lane];
    float4 x;
    x.x = acc.x * inv + b4.x; x.y = acc.y * inv + b4.y;
    x.z = acc.z * inv + b4.z; x.w = acc.w * inv + b4.w;

    float s = x.x + x.y + x.z + x.w;
#pragma unroll
    for (int off = 16; off; off >>= 1) s += __shfl_xor_sync(0xffffffffu, s, off);
    float mu = s * (1.f / 128.f);
    float dx0 = x.x - mu, dx1 = x.y - mu, dx2 = x.z - mu, dx3 = x.w - mu;
    float ss = dx0 * dx0 + dx1 * dx1 + dx2 * dx2 + dx3 * dx3;
#pragma unroll
    for (int off = 16; off; off >>= 1) ss += __shfl_xor_sync(0xffffffffu, ss, off);
    float istd = rsqrtf(ss * (1.f / 128.f) + LN_EPS);

    float4 g4 = ((const float4*)gamma)[lane];
    float4 be4 = ((const float4*)beta)[lane];
    float4 y;
    y.x = g4.x * dx0 * istd + be4.x;
    y.y = g4.y * dx1 * istd + be4.y;
    y.z = g4.z * dx2 * istd + be4.z;
    y.w = g4.w * dx3 * istd + be4.w;
    ((float4*)(out + (size_t)gwarp * 128))[lane] = y;
}

// ---------------- launch: fork CSR-build chain onto side stream, overlap with gemm ----------------
extern "C" void kernel_launch(void* const* d_in, const int* in_sizes, int n_in,
                              void* d_out, int out_size) {
    const float* h      = (const float*)d_in[0];
    const int*   src    = (const int*)d_in[1];
    const int*   dst    = (const int*)d_in[2];
    const float* W      = (const float*)d_in[3];
    const float* attn_l = (const float*)d_in[4];
    const float* attn_r = (const float*)d_in[5];
    const float* bias   = (const float*)d_in[6];
    const float* gamma  = (const float*)d_in[7];
    const float* beta   = (const float*)d_in[8];
    float* out = (float*)d_out;

    static cudaStream_t s1 = nullptr;
    static cudaEvent_t evRoot = nullptr, evSide = nullptr;
    if (!s1) {
        cudaStreamCreateWithFlags(&s1, cudaStreamNonBlocking);
        cudaEventCreateWithFlags(&evRoot, cudaEventDisableTiming);
        cudaEventCreateWithFlags(&evSide, cudaEventDisableTiming);
    }

    // fork: CSR-build chain on s1, gemm on the main (capture) stream
    cudaEventRecord(evRoot, 0);
    cudaStreamWaitEvent(s1, evRoot, 0);

    zero_deg_kernel<<<(NN + 255) / 256, 256, 0, s1>>>();
    hist_kernel<<<(EE + 255) / 256, 256, 0, s1>>>(dst);
    chunk_sum_kernel<<<NCHUNK, 256, 0, s1>>>();
    scan_chunks_kernel<<<1, 128, 0, s1>>>();
    scan_final_kernel<<<NCHUNK, 1024, 0, s1>>>();
    cudaEventRecord(evSide, s1);

    gemm_kernel<<<(NN + 63) / 64, 256>>>(h, W, attn_l, attn_r);

    // join: scatter needs both gemm (el/er) and cursor (scan chain)
    cudaStreamWaitEvent(0, evSide, 0);
    scatter_kernel<<<(EE + 255) / 256, 256>>>(src, dst);
    agg_ln_kernel<<<(NN * 32 + 255) / 256, 256>>>(bias, gamma, beta, out);
}